// round 5
// baseline (speedup 1.0000x reference)
#include <cuda_runtime.h>
#include <cuda_fp16.h>
#include <cstdint>

// ============================================================
// out = diag(1/(rowsum(adj)+beta)) @ (adj + diag(beta)) @ x @ W + bias
// Plan: y = x@W (fp32 SIMT, small) ; C = adj@y via legacy mma.sync fp16
// (fp32 accum). Rowsum fused into the A-tile load path (fp32 before cvt).
// Epilogue fused: out = scale*(C + beta*y) + bias.
// NOTE: no tcgen05/TMA — harness PTX target is sm_103 (no 'a' features).
// R4->R5 fix: main-loop A-tile STS dereferenced a cvta.to.shared 32-bit
// address as a generic pointer (illegal access). Now stores via generic
// pointer arithmetic on As. cp.async keeps using the u32 shared address.
// ============================================================

#define NN 8192
#define FF 256
#define MT 64            // CTA M tile
#define KS 32            // K per stage
#define NITER (NN / KS)  // 256
#define KSP 40           // padded K stride in halves (80 B, bank-conflict free)
#define AS_STAGE (MT * KSP)        // halves per A stage  (2560)
#define BS_STAGE (FF * KSP)        // halves per B stage  (10240)
#define AS_STAGE_B (AS_STAGE * 2)  // 5120 bytes
#define BS_STAGE_B (BS_STAGE * 2)  // 20480 bytes

// smem byte offsets (dynamic)
#define OFF_BIAS  0      // 256 f32
#define OFF_RS    1024   // 64 f32
#define OFF_SCALE 1280   // 64 f32
#define OFF_BETA  1536   // 64 f32
#define OFF_AS    2048                     // 2 stages * 5120  = 10240
#define OFF_BS    (OFF_AS + 2 * AS_STAGE_B) // 4 stages * 20480 = 81920
#define SMEM_TOTAL (OFF_BS + 4 * BS_STAGE_B) // 94208

// scratch (allocation-free rule: device globals) — vector accesses require
// 16B alignment; __device__ globals only guarantee type alignment.
__device__ __align__(256) float  g_y[NN * FF];    // y [node][feat] fp32
__device__ __align__(256) __half g_yhT[NN * FF];  // yT [feat n][node k] half

// ---------------- helpers ----------------
__device__ __forceinline__ uint32_t smem_u32(const void* p) {
    uint32_t a;
    asm("{ .reg .u64 t; cvta.to.shared.u64 t, %1; cvt.u32.u64 %0, t; }" : "=r"(a) : "l"(p));
    return a;
}
__device__ __forceinline__ void cp16(uint32_t dst, const void* src) {
    asm volatile("cp.async.cg.shared.global [%0], [%1], 16;" :: "r"(dst), "l"(src));
}
__device__ __forceinline__ void cp_commit() {
    asm volatile("cp.async.commit_group;" ::: "memory");
}
__device__ __forceinline__ void mma_f16(float* c, const uint32_t* a, uint32_t b0, uint32_t b1) {
    asm volatile(
        "mma.sync.aligned.m16n8k16.row.col.f32.f16.f16.f32 "
        "{%0,%1,%2,%3}, {%4,%5,%6,%7}, {%8,%9}, {%0,%1,%2,%3};"
        : "+f"(c[0]), "+f"(c[1]), "+f"(c[2]), "+f"(c[3])
        : "r"(a[0]), "r"(a[1]), "r"(a[2]), "r"(a[3]), "r"(b0), "r"(b1));
}

// ---------------- kernel A: y = x @ W (fp32), writes g_y + g_yhT ----------------
__global__ void __launch_bounds__(256) gemm_y_kernel(const float* __restrict__ x,
                                                     const float* __restrict__ w)
{
    __shared__ float xs[64][16];
    __shared__ float ws[16][64];
    __shared__ float ts[64][65];
    const int tx = threadIdx.x & 15, ty = threadIdx.x >> 4;
    const int m0 = blockIdx.y * 64, n0 = blockIdx.x * 64;
    float acc[4][4] = {};
    for (int k0 = 0; k0 < FF; k0 += 16) {
        {
            int r = threadIdx.x >> 2, c = (threadIdx.x & 3) * 4;
            *(float4*)&xs[r][c] = *(const float4*)&x[(size_t)(m0 + r) * FF + k0 + c];
            int r2 = threadIdx.x >> 4, c2 = (threadIdx.x & 15) * 4;
            *(float4*)&ws[r2][c2] = *(const float4*)&w[(size_t)(k0 + r2) * FF + n0 + c2];
        }
        __syncthreads();
        #pragma unroll
        for (int k = 0; k < 16; k++) {
            float4 b4 = *(float4*)&ws[k][tx * 4];
            float b[4] = {b4.x, b4.y, b4.z, b4.w};
            float a[4];
            #pragma unroll
            for (int ii = 0; ii < 4; ii++) a[ii] = xs[ty * 4 + ii][k];
            #pragma unroll
            for (int ii = 0; ii < 4; ii++)
                #pragma unroll
                for (int jj = 0; jj < 4; jj++)
                    acc[ii][jj] += a[ii] * b[jj];
        }
        __syncthreads();
    }
    // fp32 y (row-major) + stage into smem for the half transpose
    #pragma unroll
    for (int ii = 0; ii < 4; ii++) {
        const int m = m0 + ty * 4 + ii;
        *(float4*)&g_y[(size_t)m * FF + n0 + tx * 4] =
            make_float4(acc[ii][0], acc[ii][1], acc[ii][2], acc[ii][3]);
        #pragma unroll
        for (int jj = 0; jj < 4; jj++)
            ts[ty * 4 + ii][tx * 4 + jj] = acc[ii][jj];
    }
    __syncthreads();
    // half transpose: g_yhT[n][k]
    const int nl = threadIdx.x >> 2;          // 0..63 (local n)
    const int mq = (threadIdx.x & 3) * 16;    // 0,16,32,48 (local m)
    #pragma unroll
    for (int u = 0; u < 16; u += 8) {
        __half2 h[4];
        #pragma unroll
        for (int q = 0; q < 4; q++)
            h[q] = __floats2half2_rn(ts[mq + u + q * 2][nl], ts[mq + u + q * 2 + 1][nl]);
        uint4 pack = make_uint4(*(uint32_t*)&h[0], *(uint32_t*)&h[1],
                                *(uint32_t*)&h[2], *(uint32_t*)&h[3]);
        *(uint4*)&g_yhT[(size_t)(n0 + nl) * NN + m0 + mq + u] = pack;
    }
}

// ---------------- kernel B: C = adj @ y (fp16 HMMA) + fused epilogue ----------------
__global__ void __launch_bounds__(256, 1) gcn_mma_kernel(
    const float* __restrict__ adj,
    const float* __restrict__ beta,
    const float* __restrict__ bias,
    float* __restrict__ out)
{
    extern __shared__ char smem[];
    float* bias_s  = (float*)(smem + OFF_BIAS);
    float* rs_s    = (float*)(smem + OFF_RS);
    float* scale_s = (float*)(smem + OFF_SCALE);
    float* beta_s  = (float*)(smem + OFF_BETA);
    __half* As     = (__half*)(smem + OFF_AS);
    __half* Bs     = (__half*)(smem + OFF_BS);
    const uint32_t sb = smem_u32(smem);

    const int tid = threadIdx.x;
    const int wid = tid >> 5, lane = tid & 31;
    const int g = lane >> 2, t = lane & 3;
    const int wm = wid & 1, wn = wid >> 1;     // 2 m-warps x 4 n-warps
    const int m0 = blockIdx.x * MT;

    bias_s[tid] = bias[tid];

    // A-load mapping: thread -> fixed row ar, 8-col chunk acq*8
    const int ar = tid >> 2, acq = tid & 3;
    const float* aptr = adj + (size_t)(m0 + ar) * NN + acq * 8;
    // A-store destination: GENERIC pointer (NOT the cvta.to.shared u32!)
    __half* const a_st = As + ar * KSP + acq * 8;
    // B-load mapping: thread -> n row tid. cp.async dst uses u32 shared addr.
    const __half* bptr = g_yhT + (size_t)tid * NN;
    const uint32_t b_dst = sb + OFF_BS + tid * (KSP * 2);

    float rs_local = 0.f;
    float acc[2][8][4];
    #pragma unroll
    for (int i = 0; i < 2; i++)
        #pragma unroll
        for (int j = 0; j < 8; j++)
            #pragma unroll
            for (int q = 0; q < 4; q++) acc[i][j][q] = 0.f;

    float4 ra0[2], ra1[2];

    // ---- prologue: B stages 0..2 via cp.async, A stages 0..1 via LDG ----
    #pragma unroll
    for (int s = 0; s < 3; s++) {
        #pragma unroll
        for (int q = 0; q < 4; q++)
            cp16(b_dst + s * BS_STAGE_B + q * 16, (const void*)(bptr + s * KS + q * 8));
        cp_commit();
    }
    #pragma unroll
    for (int s = 0; s < 2; s++) {
        ra0[s] = *(const float4*)(aptr + (size_t)s * KS);
        ra1[s] = *(const float4*)(aptr + (size_t)s * KS + 4);
        rs_local += ra0[s].x + ra0[s].y + ra0[s].z + ra0[s].w
                  + ra1[s].x + ra1[s].y + ra1[s].z + ra1[s].w;
    }
    {   // STS A stage 0 (no one reads before iter-0 sync)
        __half2 h[4];
        h[0] = __floats2half2_rn(ra0[0].x, ra0[0].y);
        h[1] = __floats2half2_rn(ra0[0].z, ra0[0].w);
        h[2] = __floats2half2_rn(ra1[0].x, ra1[0].y);
        h[3] = __floats2half2_rn(ra1[0].z, ra1[0].w);
        *(uint4*)a_st =
            make_uint4(*(uint32_t*)&h[0], *(uint32_t*)&h[1], *(uint32_t*)&h[2], *(uint32_t*)&h[3]);
    }

    // ---- main loop ----
    for (int i = 0; i < NITER; i++) {
        const int abuf = i & 1;
        const int bbuf = i & 3;

        // issue LDG for A stage i+2 (into the reg set already flushed to smem)
        if (i + 2 < NITER) {
            const float* ap = aptr + (size_t)(i + 2) * KS;
            ra0[i & 1] = *(const float4*)(ap);
            ra1[i & 1] = *(const float4*)(ap + 4);
        }

        // wait for B(i)
        if (i < NITER - 2)      { asm volatile("cp.async.wait_group 2;" ::: "memory"); }
        else if (i == NITER - 2){ asm volatile("cp.async.wait_group 1;" ::: "memory"); }
        else                    { asm volatile("cp.async.wait_group 0;" ::: "memory"); }
        __syncthreads();   // all warps done with stage i-1 buffers; B(i)/A(i) visible

        // STS A(i+1) into As[(i+1)&1] (post-sync; opposite buffer from compute(i))
        if (i + 1 < NITER) {
            const float4 v0 = ra0[(i + 1) & 1], v1 = ra1[(i + 1) & 1];
            __half2 h[4];
            h[0] = __floats2half2_rn(v0.x, v0.y);
            h[1] = __floats2half2_rn(v0.z, v0.w);
            h[2] = __floats2half2_rn(v1.x, v1.y);
            h[3] = __floats2half2_rn(v1.z, v1.w);
            *(uint4*)(a_st + ((i + 1) & 1) * AS_STAGE) = make_uint4(
                *(uint32_t*)&h[0], *(uint32_t*)&h[1], *(uint32_t*)&h[2], *(uint32_t*)&h[3]);
        }
        // rowsum for stage i+2 (fp32, pre-conversion values)
        if (i + 2 < NITER) {
            const float4 v0 = ra0[i & 1], v1 = ra1[i & 1];
            rs_local += v0.x + v0.y + v0.z + v0.w + v1.x + v1.y + v1.z + v1.w;
        }
        // cp.async B(i+3) into Bs[(i+3)&3] (post-sync: last read was compute(i-1))
        if (i + 3 < NITER) {
            const uint32_t bd = b_dst + ((i + 3) & 3) * BS_STAGE_B;
            const __half* bp = bptr + (size_t)(i + 3) * KS;
            #pragma unroll
            for (int q = 0; q < 4; q++) cp16(bd + q * 16, (const void*)(bp + q * 8));
            cp_commit();
        }

        // ---- compute on stage i ----
        const __half* A_s = As + abuf * AS_STAGE;
        const __half* B_s = Bs + bbuf * BS_STAGE;
        #pragma unroll
        for (int kk = 0; kk < KS; kk += 16) {
            uint32_t a[2][4];
            #pragma unroll
            for (int mi = 0; mi < 2; mi++) {
                const int row = wm * 32 + mi * 16 + g;
                a[mi][0] = *(const uint32_t*)&A_s[(row)     * KSP + kk + 2 * t];
                a[mi][1] = *(const uint32_t*)&A_s[(row + 8) * KSP + kk + 2 * t];
                a[mi][2] = *(const uint32_t*)&A_s[(row)     * KSP + kk + 8 + 2 * t];
                a[mi][3] = *(const uint32_t*)&A_s[(row + 8) * KSP + kk + 8 + 2 * t];
            }
            #pragma unroll
            for (int nj = 0; nj < 8; nj++) {
                const int ncol = wn * 64 + nj * 8 + g;
                const uint32_t b0 = *(const uint32_t*)&B_s[ncol * KSP + kk + 2 * t];
                const uint32_t b1 = *(const uint32_t*)&B_s[ncol * KSP + kk + 8 + 2 * t];
                mma_f16(acc[0][nj], a[0], b0, b1);
                mma_f16(acc[1][nj], a[1], b0, b1);
            }
        }
    }

    // ---- rowsum reduce (4 threads per row, consecutive lanes) ----
    float rs = rs_local;
    rs += __shfl_xor_sync(0xffffffffu, rs, 1);
    rs += __shfl_xor_sync(0xffffffffu, rs, 2);
    if ((tid & 3) == 0) rs_s[ar] = rs;
    __syncthreads();
    if (tid < MT) {
        const float be = beta[m0 + tid];
        beta_s[tid] = be;
        scale_s[tid] = 1.0f / (rs_s[tid] + be);
    }
    __syncthreads();

    // ---- epilogue: out = scale*(C + beta*y) + bias ----
    #pragma unroll
    for (int mi = 0; mi < 2; mi++) {
        const int lm = wm * 32 + mi * 16 + g;
        const float sc0 = scale_s[lm],     be0 = beta_s[lm];
        const float sc1 = scale_s[lm + 8], be1 = beta_s[lm + 8];
        #pragma unroll
        for (int nj = 0; nj < 8; nj++) {
            const int n = wn * 64 + nj * 8 + 2 * t;
            const size_t base0 = (size_t)(m0 + lm) * FF + n;
            const size_t base1 = (size_t)(m0 + lm + 8) * FF + n;
            const float2 y0 = *(const float2*)&g_y[base0];
            const float2 y1 = *(const float2*)&g_y[base1];
            float2 o0, o1;
            o0.x = sc0 * (acc[mi][nj][0] + be0 * y0.x) + bias_s[n];
            o0.y = sc0 * (acc[mi][nj][1] + be0 * y0.y) + bias_s[n + 1];
            o1.x = sc1 * (acc[mi][nj][2] + be1 * y1.x) + bias_s[n];
            o1.y = sc1 * (acc[mi][nj][3] + be1 * y1.y) + bias_s[n + 1];
            *(float2*)&out[base0] = o0;
            *(float2*)&out[base1] = o1;
        }
    }
}

// ---------------- launch ----------------
extern "C" void kernel_launch(void* const* d_in, const int* in_sizes, int n_in,
                              void* d_out, int out_size)
{
    const float *x = nullptr, *adj = nullptr, *w = nullptr, *bias = nullptr, *beta = nullptr;
    for (int i = 0; i < n_in; i++) {
        switch (in_sizes[i]) {
            case NN * FF:   x    = (const float*)d_in[i]; break; // 2097152
            case 67108864:  adj  = (const float*)d_in[i]; break; // 8192*8192
            case FF * FF:   w    = (const float*)d_in[i]; break; // 65536
            case FF:        bias = (const float*)d_in[i]; break; // 256
            case NN:        beta = (const float*)d_in[i]; break; // 8192
            default: break;
        }
    }
    float* out = (float*)d_out;

    cudaFuncSetAttribute(gcn_mma_kernel, cudaFuncAttributeMaxDynamicSharedMemorySize, SMEM_TOTAL);

    gemm_y_kernel<<<dim3(FF / 64, NN / 64), 256>>>(x, w);
    gcn_mma_kernel<<<NN / MT, 256, SMEM_TOTAL>>>(adj, beta, bias, out);
}

// round 6
// speedup vs baseline: 1.2959x; 1.2959x over previous
#include <cuda_runtime.h>
#include <cuda_fp16.h>
#include <cstdint>

// ============================================================
// out = diag(1/(rowsum(adj)+beta)) @ (adj + diag(beta)) @ x @ W + bias
// y = x@W (fp32 SIMT); C = adj@y via mma.sync fp16 (fp32 accum), rowsum
// fused into the A-load path; epilogue: out = scale*(C + beta*y) + bias.
// R5->R6: inner loop rebuilt on ldmatrix.x4 (was 48 scalar LDS/warp-iter,
// short-scoreboard bound at 12.9% tensor util); K-stage 32->64 halves
// barrier count and doubles A-LDG slack.
// ============================================================

#define NN 8192
#define FF 256
#define MT 64             // CTA M tile
#define KS 64             // K per stage
#define NITER (NN / KS)   // 128
#define KSP 72            // padded K stride in halves (144 B, conflict-free)
#define AS_STAGE (MT * KSP)        // 4608 halves
#define BS_STAGE (FF * KSP)        // 18432 halves
#define AS_STAGE_B (AS_STAGE * 2)  // 9216 B
#define BS_STAGE_B (BS_STAGE * 2)  // 36864 B

#define OFF_BIAS  0
#define OFF_RS    1024
#define OFF_SCALE 1280
#define OFF_BETA  1536
#define OFF_AS    2048                       // 2 stages
#define OFF_BS    (OFF_AS + 2 * AS_STAGE_B)  // 20480, 3 stages
#define SMEM_TOTAL (OFF_BS + 3 * BS_STAGE_B) // 131072

__device__ __align__(256) float  g_y[NN * FF];    // y [node][feat] fp32
__device__ __align__(256) __half g_yhT[NN * FF];  // yT [feat n][node k] half

// ---------------- helpers ----------------
__device__ __forceinline__ uint32_t smem_u32(const void* p) {
    uint32_t a;
    asm("{ .reg .u64 t; cvta.to.shared.u64 t, %1; cvt.u32.u64 %0, t; }" : "=r"(a) : "l"(p));
    return a;
}
__device__ __forceinline__ void cp16(uint32_t dst, const void* src) {
    asm volatile("cp.async.cg.shared.global [%0], [%1], 16;" :: "r"(dst), "l"(src));
}
__device__ __forceinline__ void cp_commit() {
    asm volatile("cp.async.commit_group;" ::: "memory");
}
__device__ __forceinline__ void ldm_x4(uint32_t* r, uint32_t addr) {
    asm volatile("ldmatrix.sync.aligned.m8n8.x4.shared.b16 {%0,%1,%2,%3}, [%4];"
        : "=r"(r[0]), "=r"(r[1]), "=r"(r[2]), "=r"(r[3]) : "r"(addr));
}
__device__ __forceinline__ void mma_f16(float* c, const uint32_t* a, uint32_t b0, uint32_t b1) {
    asm volatile(
        "mma.sync.aligned.m16n8k16.row.col.f32.f16.f16.f32 "
        "{%0,%1,%2,%3}, {%4,%5,%6,%7}, {%8,%9}, {%0,%1,%2,%3};"
        : "+f"(c[0]), "+f"(c[1]), "+f"(c[2]), "+f"(c[3])
        : "r"(a[0]), "r"(a[1]), "r"(a[2]), "r"(a[3]), "r"(b0), "r"(b1));
}

// ---------------- kernel A: y = x @ W (fp32), writes g_y + g_yhT ----------------
__global__ void __launch_bounds__(256) gemm_y_kernel(const float* __restrict__ x,
                                                     const float* __restrict__ w)
{
    __shared__ float xs[64][16];
    __shared__ float ws[16][64];
    __shared__ float ts[64][65];
    const int tx = threadIdx.x & 15, ty = threadIdx.x >> 4;
    const int m0 = blockIdx.y * 64, n0 = blockIdx.x * 64;
    float acc[4][4] = {};
    for (int k0 = 0; k0 < FF; k0 += 16) {
        {
            int r = threadIdx.x >> 2, c = (threadIdx.x & 3) * 4;
            *(float4*)&xs[r][c] = *(const float4*)&x[(size_t)(m0 + r) * FF + k0 + c];
            int r2 = threadIdx.x >> 4, c2 = (threadIdx.x & 15) * 4;
            *(float4*)&ws[r2][c2] = *(const float4*)&w[(size_t)(k0 + r2) * FF + n0 + c2];
        }
        __syncthreads();
        #pragma unroll
        for (int k = 0; k < 16; k++) {
            float4 b4 = *(float4*)&ws[k][tx * 4];
            float b[4] = {b4.x, b4.y, b4.z, b4.w};
            float a[4];
            #pragma unroll
            for (int ii = 0; ii < 4; ii++) a[ii] = xs[ty * 4 + ii][k];
            #pragma unroll
            for (int ii = 0; ii < 4; ii++)
                #pragma unroll
                for (int jj = 0; jj < 4; jj++)
                    acc[ii][jj] += a[ii] * b[jj];
        }
        __syncthreads();
    }
    #pragma unroll
    for (int ii = 0; ii < 4; ii++) {
        const int m = m0 + ty * 4 + ii;
        *(float4*)&g_y[(size_t)m * FF + n0 + tx * 4] =
            make_float4(acc[ii][0], acc[ii][1], acc[ii][2], acc[ii][3]);
        #pragma unroll
        for (int jj = 0; jj < 4; jj++)
            ts[ty * 4 + ii][tx * 4 + jj] = acc[ii][jj];
    }
    __syncthreads();
    const int nl = threadIdx.x >> 2;
    const int mq = (threadIdx.x & 3) * 16;
    #pragma unroll
    for (int u = 0; u < 16; u += 8) {
        __half2 h[4];
        #pragma unroll
        for (int q = 0; q < 4; q++)
            h[q] = __floats2half2_rn(ts[mq + u + q * 2][nl], ts[mq + u + q * 2 + 1][nl]);
        uint4 pack = make_uint4(*(uint32_t*)&h[0], *(uint32_t*)&h[1],
                                *(uint32_t*)&h[2], *(uint32_t*)&h[3]);
        *(uint4*)&g_yhT[(size_t)(n0 + nl) * NN + m0 + mq + u] = pack;
    }
}

// ---------------- kernel B: C = adj @ y (fp16 HMMA, ldmatrix) + epilogue ----------------
__global__ void __launch_bounds__(256, 1) gcn_mma_kernel(
    const float* __restrict__ adj,
    const float* __restrict__ beta,
    const float* __restrict__ bias,
    float* __restrict__ out)
{
    extern __shared__ char smem[];
    float* bias_s  = (float*)(smem + OFF_BIAS);
    float* rs_s    = (float*)(smem + OFF_RS);
    float* scale_s = (float*)(smem + OFF_SCALE);
    float* beta_s  = (float*)(smem + OFF_BETA);
    __half* As     = (__half*)(smem + OFF_AS);
    const uint32_t sb = smem_u32(smem);

    const int tid = threadIdx.x;
    const int wid = tid >> 5, lane = tid & 31;
    const int g = lane >> 2, t = lane & 3;
    const int wm = wid & 1, wn = wid >> 1;     // 2 m-warps x 4 n-warps
    const int m0 = blockIdx.x * MT;

    bias_s[tid] = bias[tid];

    // A-load mapping: thread -> row ar, 16-float chunk at acq*16
    const int ar = tid >> 2, acq = tid & 3;
    const float* aptr = adj + (size_t)(m0 + ar) * NN + acq * 16;
    __half* const a_st = As + ar * KSP + acq * 16;   // generic pointer for STS
    // B: thread -> n row tid; cp.async dst uses u32 shared address
    const __half* bptr = g_yhT + (size_t)tid * NN;
    const uint32_t b_dst = sb + OFF_BS + tid * (KSP * 2);

    // ldmatrix lane base addresses (bytes)
    const int mt8 = lane >> 3, r8 = lane & 7;
    const uint32_t a_lm = sb + OFF_AS +
        (((wm * 32 + (mt8 & 1) * 8 + r8) * KSP + (mt8 >> 1) * 8) * 2);
    const uint32_t b_lm = sb + OFF_BS +
        (((wn * 64 + (mt8 >> 1) * 8 + r8) * KSP + (mt8 & 1) * 8) * 2);

    float rs_local = 0.f;
    float acc[2][8][4];
    #pragma unroll
    for (int i = 0; i < 2; i++)
        #pragma unroll
        for (int j = 0; j < 8; j++)
            #pragma unroll
            for (int q = 0; q < 4; q++) acc[i][j][q] = 0.f;

    float4 ra[2][4];

    // ---- prologue ----
    #pragma unroll
    for (int s = 0; s < 2; s++) {               // B stages 0,1
        #pragma unroll
        for (int q = 0; q < 8; q++)
            cp16(b_dst + s * BS_STAGE_B + q * 16, (const void*)(bptr + s * KS + q * 8));
        cp_commit();
    }
    #pragma unroll
    for (int s = 0; s < 2; s++)                 // A stages 0,1 -> regs
        #pragma unroll
        for (int q = 0; q < 4; q++)
            ra[s][q] = *(const float4*)(aptr + (size_t)s * KS + q * 4);
    {   // STS A stage 0 + rowsum stage 0
        __half2 h[8];
        #pragma unroll
        for (int q = 0; q < 4; q++) {
            const float4 v = ra[0][q];
            h[q * 2]     = __floats2half2_rn(v.x, v.y);
            h[q * 2 + 1] = __floats2half2_rn(v.z, v.w);
            rs_local += v.x + v.y + v.z + v.w;
        }
        *(uint4*)a_st       = make_uint4(*(uint32_t*)&h[0], *(uint32_t*)&h[1],
                                         *(uint32_t*)&h[2], *(uint32_t*)&h[3]);
        *(uint4*)(a_st + 8) = make_uint4(*(uint32_t*)&h[4], *(uint32_t*)&h[5],
                                         *(uint32_t*)&h[6], *(uint32_t*)&h[7]);
    }

    // ---- main loop ----
    for (int i = 0; i < NITER; i++) {
        const int abuf = i & 1;
        const int bbuf = i % 3;

        // LDG A stage i+2 into ra[i&1] (stage i already flushed at iter i-1)
        if (i + 2 < NITER) {
            const float* ap = aptr + (size_t)(i + 2) * KS;
            #pragma unroll
            for (int q = 0; q < 4; q++) ra[i & 1][q] = *(const float4*)(ap + q * 4);
        }

        if (i < NITER - 1) { asm volatile("cp.async.wait_group 1;" ::: "memory"); }
        else               { asm volatile("cp.async.wait_group 0;" ::: "memory"); }
        __syncthreads();

        // STS A stage i+1 (regs loaded at iter i-1) + its rowsum
        if (i + 1 < NITER) {
            __half2 h[8];
            #pragma unroll
            for (int q = 0; q < 4; q++) {
                const float4 v = ra[(i + 1) & 1][q];
                h[q * 2]     = __floats2half2_rn(v.x, v.y);
                h[q * 2 + 1] = __floats2half2_rn(v.z, v.w);
                rs_local += v.x + v.y + v.z + v.w;
            }
            __half* dst = a_st + ((i + 1) & 1) * AS_STAGE;
            *(uint4*)dst       = make_uint4(*(uint32_t*)&h[0], *(uint32_t*)&h[1],
                                            *(uint32_t*)&h[2], *(uint32_t*)&h[3]);
            *(uint4*)(dst + 8) = make_uint4(*(uint32_t*)&h[4], *(uint32_t*)&h[5],
                                            *(uint32_t*)&h[6], *(uint32_t*)&h[7]);
        }
        // cp.async B stage i+2 into buffer (i+2)%3
        if (i + 2 < NITER) {
            const uint32_t bd = b_dst + ((i + 2) % 3) * BS_STAGE_B;
            const __half* bp = bptr + (size_t)(i + 2) * KS;
            #pragma unroll
            for (int q = 0; q < 8; q++) cp16(bd + q * 16, (const void*)(bp + q * 8));
            cp_commit();
        }

        // ---- compute on stage i ----
        const uint32_t aB = a_lm + abuf * AS_STAGE_B;
        const uint32_t bB = b_lm + bbuf * BS_STAGE_B;
        #pragma unroll
        for (int kk = 0; kk < KS; kk += 16) {
            uint32_t a0[4], a1[4];
            ldm_x4(a0, aB + kk * 2);
            ldm_x4(a1, aB + kk * 2 + 16 * KSP * 2);
            uint32_t bf[4][4];
            #pragma unroll
            for (int p = 0; p < 4; p++)
                ldm_x4(bf[p], bB + kk * 2 + p * 16 * KSP * 2);
            #pragma unroll
            for (int p = 0; p < 4; p++) {
                mma_f16(acc[0][2 * p],     a0, bf[p][0], bf[p][1]);
                mma_f16(acc[1][2 * p],     a1, bf[p][0], bf[p][1]);
                mma_f16(acc[0][2 * p + 1], a0, bf[p][2], bf[p][3]);
                mma_f16(acc[1][2 * p + 1], a1, bf[p][2], bf[p][3]);
            }
        }
    }

    // ---- rowsum reduce (4 threads per row) ----
    float rs = rs_local;
    rs += __shfl_xor_sync(0xffffffffu, rs, 1);
    rs += __shfl_xor_sync(0xffffffffu, rs, 2);
    if ((tid & 3) == 0) rs_s[ar] = rs;
    __syncthreads();
    if (tid < MT) {
        const float be = beta[m0 + tid];
        beta_s[tid] = be;
        scale_s[tid] = 1.0f / (rs_s[tid] + be);
    }
    __syncthreads();

    // ---- epilogue: out = scale*(C + beta*y) + bias ----
    #pragma unroll
    for (int mi = 0; mi < 2; mi++) {
        const int lm = wm * 32 + mi * 16 + g;
        const float sc0 = scale_s[lm],     be0 = beta_s[lm];
        const float sc1 = scale_s[lm + 8], be1 = beta_s[lm + 8];
        #pragma unroll
        for (int nj = 0; nj < 8; nj++) {
            const int n = wn * 64 + nj * 8 + 2 * t;
            const size_t base0 = (size_t)(m0 + lm) * FF + n;
            const size_t base1 = (size_t)(m0 + lm + 8) * FF + n;
            const float2 y0 = *(const float2*)&g_y[base0];
            const float2 y1 = *(const float2*)&g_y[base1];
            float2 o0, o1;
            o0.x = sc0 * (acc[mi][nj][0] + be0 * y0.x) + bias_s[n];
            o0.y = sc0 * (acc[mi][nj][1] + be0 * y0.y) + bias_s[n + 1];
            o1.x = sc1 * (acc[mi][nj][2] + be1 * y1.x) + bias_s[n];
            o1.y = sc1 * (acc[mi][nj][3] + be1 * y1.y) + bias_s[n + 1];
            *(float2*)&out[base0] = o0;
            *(float2*)&out[base1] = o1;
        }
    }
}

// ---------------- launch ----------------
extern "C" void kernel_launch(void* const* d_in, const int* in_sizes, int n_in,
                              void* d_out, int out_size)
{
    const float *x = nullptr, *adj = nullptr, *w = nullptr, *bias = nullptr, *beta = nullptr;
    for (int i = 0; i < n_in; i++) {
        switch (in_sizes[i]) {
            case NN * FF:   x    = (const float*)d_in[i]; break;
            case 67108864:  adj  = (const float*)d_in[i]; break;
            case FF * FF:   w    = (const float*)d_in[i]; break;
            case FF:        bias = (const float*)d_in[i]; break;
            case NN:        beta = (const float*)d_in[i]; break;
            default: break;
        }
    }
    float* out = (float*)d_out;

    cudaFuncSetAttribute(gcn_mma_kernel, cudaFuncAttributeMaxDynamicSharedMemorySize, SMEM_TOTAL);

    gemm_y_kernel<<<dim3(FF / 64, NN / 64), 256>>>(x, w);
    gcn_mma_kernel<<<NN / MT, 256, SMEM_TOTAL>>>(adj, beta, bias, out);
}

// round 7
// speedup vs baseline: 1.5657x; 1.2082x over previous
#include <cuda_runtime.h>
#include <cuda_fp16.h>
#include <cstdint>

// ============================================================
// out = diag(1/(rowsum(adj)+beta)) @ (adj + diag(beta)) @ x @ W + bias
// y = x@W (fp32 SIMT); C = adj@y via mma.sync fp16 (fp32 accum), rowsum
// fused into the A-load path; epilogue: out = scale*(C + beta*y) + bias.
// R6->R7: 256 -> 512 threads (16 warps, 2m x 8n, warp tile 32x32).
// Profile showed latency-bound at 2 warps/SMSP (occ 12.4%, issue 7.6%,
// tensor 17%); same tiles/traffic, double the latency-hiding warps.
// ============================================================

#define NN 8192
#define FF 256
#define MT 64             // CTA M tile
#define KS 64             // K per stage
#define NITER (NN / KS)   // 128
#define KSP 72            // padded K stride in halves (144 B, conflict-free)
#define AS_STAGE (MT * KSP)        // 4608 halves
#define BS_STAGE (FF * KSP)        // 18432 halves
#define AS_STAGE_B (AS_STAGE * 2)  // 9216 B
#define BS_STAGE_B (BS_STAGE * 2)  // 36864 B

#define OFF_BIAS  0
#define OFF_RS    1024
#define OFF_SCALE 1280
#define OFF_BETA  1536
#define OFF_AS    2048                       // 2 stages
#define OFF_BS    (OFF_AS + 2 * AS_STAGE_B)  // 20480, 3 stages
#define SMEM_TOTAL (OFF_BS + 3 * BS_STAGE_B) // 131072

__device__ __align__(256) float  g_y[NN * FF];    // y [node][feat] fp32
__device__ __align__(256) __half g_yhT[NN * FF];  // yT [feat n][node k] half

// ---------------- helpers ----------------
__device__ __forceinline__ uint32_t smem_u32(const void* p) {
    uint32_t a;
    asm("{ .reg .u64 t; cvta.to.shared.u64 t, %1; cvt.u32.u64 %0, t; }" : "=r"(a) : "l"(p));
    return a;
}
__device__ __forceinline__ void cp16(uint32_t dst, const void* src) {
    asm volatile("cp.async.cg.shared.global [%0], [%1], 16;" :: "r"(dst), "l"(src));
}
__device__ __forceinline__ void cp_commit() {
    asm volatile("cp.async.commit_group;" ::: "memory");
}
__device__ __forceinline__ void ldm_x4(uint32_t* r, uint32_t addr) {
    asm volatile("ldmatrix.sync.aligned.m8n8.x4.shared.b16 {%0,%1,%2,%3}, [%4];"
        : "=r"(r[0]), "=r"(r[1]), "=r"(r[2]), "=r"(r[3]) : "r"(addr));
}
__device__ __forceinline__ void mma_f16(float* c, const uint32_t* a, uint32_t b0, uint32_t b1) {
    asm volatile(
        "mma.sync.aligned.m16n8k16.row.col.f32.f16.f16.f32 "
        "{%0,%1,%2,%3}, {%4,%5,%6,%7}, {%8,%9}, {%0,%1,%2,%3};"
        : "+f"(c[0]), "+f"(c[1]), "+f"(c[2]), "+f"(c[3])
        : "r"(a[0]), "r"(a[1]), "r"(a[2]), "r"(a[3]), "r"(b0), "r"(b1));
}

// ---------------- kernel A: y = x @ W (fp32), writes g_y + g_yhT ----------------
__global__ void __launch_bounds__(256) gemm_y_kernel(const float* __restrict__ x,
                                                     const float* __restrict__ w)
{
    __shared__ float xs[64][16];
    __shared__ float ws[16][64];
    __shared__ float ts[64][65];
    const int tx = threadIdx.x & 15, ty = threadIdx.x >> 4;
    const int m0 = blockIdx.y * 64, n0 = blockIdx.x * 64;
    float acc[4][4] = {};
    for (int k0 = 0; k0 < FF; k0 += 16) {
        {
            int r = threadIdx.x >> 2, c = (threadIdx.x & 3) * 4;
            *(float4*)&xs[r][c] = *(const float4*)&x[(size_t)(m0 + r) * FF + k0 + c];
            int r2 = threadIdx.x >> 4, c2 = (threadIdx.x & 15) * 4;
            *(float4*)&ws[r2][c2] = *(const float4*)&w[(size_t)(k0 + r2) * FF + n0 + c2];
        }
        __syncthreads();
        #pragma unroll
        for (int k = 0; k < 16; k++) {
            float4 b4 = *(float4*)&ws[k][tx * 4];
            float b[4] = {b4.x, b4.y, b4.z, b4.w};
            float a[4];
            #pragma unroll
            for (int ii = 0; ii < 4; ii++) a[ii] = xs[ty * 4 + ii][k];
            #pragma unroll
            for (int ii = 0; ii < 4; ii++)
                #pragma unroll
                for (int jj = 0; jj < 4; jj++)
                    acc[ii][jj] += a[ii] * b[jj];
        }
        __syncthreads();
    }
    #pragma unroll
    for (int ii = 0; ii < 4; ii++) {
        const int m = m0 + ty * 4 + ii;
        *(float4*)&g_y[(size_t)m * FF + n0 + tx * 4] =
            make_float4(acc[ii][0], acc[ii][1], acc[ii][2], acc[ii][3]);
        #pragma unroll
        for (int jj = 0; jj < 4; jj++)
            ts[ty * 4 + ii][tx * 4 + jj] = acc[ii][jj];
    }
    __syncthreads();
    const int nl = threadIdx.x >> 2;
    const int mq = (threadIdx.x & 3) * 16;
    #pragma unroll
    for (int u = 0; u < 16; u += 8) {
        __half2 h[4];
        #pragma unroll
        for (int q = 0; q < 4; q++)
            h[q] = __floats2half2_rn(ts[mq + u + q * 2][nl], ts[mq + u + q * 2 + 1][nl]);
        uint4 pack = make_uint4(*(uint32_t*)&h[0], *(uint32_t*)&h[1],
                                *(uint32_t*)&h[2], *(uint32_t*)&h[3]);
        *(uint4*)&g_yhT[(size_t)(n0 + nl) * NN + m0 + mq + u] = pack;
    }
}

// ---------------- kernel B: C = adj @ y (fp16 HMMA, ldmatrix) + epilogue ----------------
__global__ void __launch_bounds__(512, 1) gcn_mma_kernel(
    const float* __restrict__ adj,
    const float* __restrict__ beta,
    const float* __restrict__ bias,
    float* __restrict__ out)
{
    extern __shared__ char smem[];
    float* bias_s  = (float*)(smem + OFF_BIAS);
    float* rs_s    = (float*)(smem + OFF_RS);
    float* scale_s = (float*)(smem + OFF_SCALE);
    float* beta_s  = (float*)(smem + OFF_BETA);
    __half* As     = (__half*)(smem + OFF_AS);
    const uint32_t sb = smem_u32(smem);

    const int tid = threadIdx.x;
    const int wid = tid >> 5, lane = tid & 31;
    const int g = lane >> 2, t = lane & 3;
    const int wm = wid & 1, wn = wid >> 1;     // 2 m-warps x 8 n-warps
    const int m0 = blockIdx.x * MT;

    if (tid < FF) bias_s[tid] = bias[tid];

    // A-load mapping: thread -> row ar (tid>>3), 8-float chunk at (tid&7)*8
    const int ar = tid >> 3, acq = tid & 7;
    const float* aptr = adj + (size_t)(m0 + ar) * NN + acq * 8;
    __half* const a_st = As + ar * KSP + acq * 8;    // generic pointer for STS
    // B: 2 threads per n-row; cp.async dst uses u32 shared address
    const __half* bptr = g_yhT + (size_t)(tid >> 1) * NN + (tid & 1) * 32;
    const uint32_t b_dst = sb + OFF_BS + (tid >> 1) * (KSP * 2) + (tid & 1) * 64;

    // ldmatrix lane base addresses (bytes)
    const int mt8 = lane >> 3, r8 = lane & 7;
    const uint32_t a_lm = sb + OFF_AS +
        (((wm * 32 + (mt8 & 1) * 8 + r8) * KSP + (mt8 >> 1) * 8) * 2);
    const uint32_t b_lm = sb + OFF_BS +
        (((wn * 32 + (mt8 >> 1) * 8 + r8) * KSP + (mt8 & 1) * 8) * 2);

    float rs_local = 0.f;
    float acc[2][4][4];
    #pragma unroll
    for (int i = 0; i < 2; i++)
        #pragma unroll
        for (int j = 0; j < 4; j++)
            #pragma unroll
            for (int q = 0; q < 4; q++) acc[i][j][q] = 0.f;

    float4 ra[2][2];

    // ---- prologue ----
    #pragma unroll
    for (int s = 0; s < 2; s++) {               // B stages 0,1
        #pragma unroll
        for (int q = 0; q < 4; q++)
            cp16(b_dst + s * BS_STAGE_B + q * 16, (const void*)(bptr + s * KS + q * 8));
        cp_commit();
    }
    #pragma unroll
    for (int s = 0; s < 2; s++) {               // A stages 0,1 -> regs
        ra[s][0] = *(const float4*)(aptr + (size_t)s * KS);
        ra[s][1] = *(const float4*)(aptr + (size_t)s * KS + 4);
    }
    {   // STS A stage 0 + rowsum stage 0
        const float4 v0 = ra[0][0], v1 = ra[0][1];
        rs_local += v0.x + v0.y + v0.z + v0.w + v1.x + v1.y + v1.z + v1.w;
        __half2 h[4];
        h[0] = __floats2half2_rn(v0.x, v0.y);
        h[1] = __floats2half2_rn(v0.z, v0.w);
        h[2] = __floats2half2_rn(v1.x, v1.y);
        h[3] = __floats2half2_rn(v1.z, v1.w);
        *(uint4*)a_st = make_uint4(*(uint32_t*)&h[0], *(uint32_t*)&h[1],
                                   *(uint32_t*)&h[2], *(uint32_t*)&h[3]);
    }

    // ---- main loop ----
    for (int i = 0; i < NITER; i++) {
        const int abuf = i & 1;
        const int bbuf = i % 3;

        // LDG A stage i+2 into ra[i&1] (stage i already flushed at iter i-1)
        if (i + 2 < NITER) {
            const float* ap = aptr + (size_t)(i + 2) * KS;
            ra[i & 1][0] = *(const float4*)(ap);
            ra[i & 1][1] = *(const float4*)(ap + 4);
        }

        if (i < NITER - 1) { asm volatile("cp.async.wait_group 1;" ::: "memory"); }
        else               { asm volatile("cp.async.wait_group 0;" ::: "memory"); }
        __syncthreads();

        // STS A stage i+1 (regs loaded at iter i-1) + its rowsum
        if (i + 1 < NITER) {
            const float4 v0 = ra[(i + 1) & 1][0], v1 = ra[(i + 1) & 1][1];
            rs_local += v0.x + v0.y + v0.z + v0.w + v1.x + v1.y + v1.z + v1.w;
            __half2 h[4];
            h[0] = __floats2half2_rn(v0.x, v0.y);
            h[1] = __floats2half2_rn(v0.z, v0.w);
            h[2] = __floats2half2_rn(v1.x, v1.y);
            h[3] = __floats2half2_rn(v1.z, v1.w);
            *(uint4*)(a_st + ((i + 1) & 1) * AS_STAGE) = make_uint4(
                *(uint32_t*)&h[0], *(uint32_t*)&h[1], *(uint32_t*)&h[2], *(uint32_t*)&h[3]);
        }
        // cp.async B stage i+2 into buffer (i+2)%3
        if (i + 2 < NITER) {
            const uint32_t bd = b_dst + ((i + 2) % 3) * BS_STAGE_B;
            const __half* bp = bptr + (size_t)(i + 2) * KS;
            #pragma unroll
            for (int q = 0; q < 4; q++) cp16(bd + q * 16, (const void*)(bp + q * 8));
            cp_commit();
        }

        // ---- compute on stage i ----
        const uint32_t aB = a_lm + abuf * AS_STAGE_B;
        const uint32_t bB = b_lm + bbuf * BS_STAGE_B;
        #pragma unroll
        for (int kk = 0; kk < KS; kk += 16) {
            uint32_t a0[4], a1[4];
            ldm_x4(a0, aB + kk * 2);
            ldm_x4(a1, aB + kk * 2 + 16 * KSP * 2);
            uint32_t bf[2][4];
            #pragma unroll
            for (int p = 0; p < 2; p++)
                ldm_x4(bf[p], bB + kk * 2 + p * 16 * KSP * 2);
            #pragma unroll
            for (int p = 0; p < 2; p++) {
                mma_f16(acc[0][2 * p],     a0, bf[p][0], bf[p][1]);
                mma_f16(acc[1][2 * p],     a1, bf[p][0], bf[p][1]);
                mma_f16(acc[0][2 * p + 1], a0, bf[p][2], bf[p][3]);
                mma_f16(acc[1][2 * p + 1], a1, bf[p][2], bf[p][3]);
            }
        }
    }

    // ---- rowsum reduce (8 threads per row) ----
    float rs = rs_local;
    rs += __shfl_xor_sync(0xffffffffu, rs, 1);
    rs += __shfl_xor_sync(0xffffffffu, rs, 2);
    rs += __shfl_xor_sync(0xffffffffu, rs, 4);
    if ((tid & 7) == 0) rs_s[ar] = rs;
    __syncthreads();
    if (tid < MT) {
        const float be = beta[m0 + tid];
        beta_s[tid] = be;
        scale_s[tid] = 1.0f / (rs_s[tid] + be);
    }
    __syncthreads();

    // ---- epilogue: out = scale*(C + beta*y) + bias ----
    #pragma unroll
    for (int mi = 0; mi < 2; mi++) {
        const int lm = wm * 32 + mi * 16 + g;
        const float sc0 = scale_s[lm],     be0 = beta_s[lm];
        const float sc1 = scale_s[lm + 8], be1 = beta_s[lm + 8];
        #pragma unroll
        for (int nj = 0; nj < 4; nj++) {
            const int n = wn * 32 + nj * 8 + 2 * t;
            const size_t base0 = (size_t)(m0 + lm) * FF + n;
            const size_t base1 = (size_t)(m0 + lm + 8) * FF + n;
            const float2 y0 = *(const float2*)&g_y[base0];
            const float2 y1 = *(const float2*)&g_y[base1];
            float2 o0, o1;
            o0.x = sc0 * (acc[mi][nj][0] + be0 * y0.x) + bias_s[n];
            o0.y = sc0 * (acc[mi][nj][1] + be0 * y0.y) + bias_s[n + 1];
            o1.x = sc1 * (acc[mi][nj][2] + be1 * y1.x) + bias_s[n];
            o1.y = sc1 * (acc[mi][nj][3] + be1 * y1.y) + bias_s[n + 1];
            *(float2*)&out[base0] = o0;
            *(float2*)&out[base1] = o1;
        }
    }
}

// ---------------- launch ----------------
extern "C" void kernel_launch(void* const* d_in, const int* in_sizes, int n_in,
                              void* d_out, int out_size)
{
    const float *x = nullptr, *adj = nullptr, *w = nullptr, *bias = nullptr, *beta = nullptr;
    for (int i = 0; i < n_in; i++) {
        switch (in_sizes[i]) {
            case NN * FF:   x    = (const float*)d_in[i]; break;
            case 67108864:  adj  = (const float*)d_in[i]; break;
            case FF * FF:   w    = (const float*)d_in[i]; break;
            case FF:        bias = (const float*)d_in[i]; break;
            case NN:        beta = (const float*)d_in[i]; break;
            default: break;
        }
    }
    float* out = (float*)d_out;

    cudaFuncSetAttribute(gcn_mma_kernel, cudaFuncAttributeMaxDynamicSharedMemorySize, SMEM_TOTAL);

    gemm_y_kernel<<<dim3(FF / 64, NN / 64), 256>>>(x, w);
    gcn_mma_kernel<<<NN / MT, 512, SMEM_TOTAL>>>(adj, beta, bias, out);
}